// round 16
// baseline (speedup 1.0000x reference)
#include <cuda_runtime.h>

// Problem constants: B=2, N=8192, T=32, C=64, K=16, NUM_BASES=4
#define Bv 2
#define Nv 8192
#define Tv 32
#define Cv 64
#define Kv 16
#define NB 4
#define TC4 (Tv * Cv / 4)   // 512 float4 per (b,n) row

// out[b,n,t,c] = tanh( sum_k z[b, nbr[n,k], t, c] * w[c,n,k] )
// w[c,n,k] = adj[n,k] * sum_base cc[c,base] * bw[base,n,k]
//
// FINAL champion (R7 shape; 127.3us, reproduced 127.7/127.5us):
//  - 64 threads/CTA; thread = (c4 = tid&15, th = tid>>4) owns channel group
//    c4 and 8 output slots s = c4 + 16*(th + 4j) -> one weight float4 per k
//    serves 8 outputs (weight-LDS amortized x8; gather wavefronts at the
//    compulsory 1024/CTA).
//  - grid (N, B): batch-major waves keep one batch's 67 MB of z L2-resident
//    (fusing batches thrashes the 126 MB L2: R11, 308us).
//  - Ascending-neighbor sweep via 16-lane bitonic sort of (nbr<<4)|k: all
//    CTAs in a wave sweep z coherently; measured DRAM traffic (~394 MB) sits
//    at the compulsory floor (~402 MB).
//  - Cooperative coalesced staging of cc/bw/adj; conflict-free LDS.128 build.
//  - __stcs output stores (evict-first): best of {plain, __stcs, __stwt}.
// Plateau proof: occupancy 23-47% (R3/R4/R6), MLP/SW-pipelining (R8), L2
// prefetch (R9, -39%), TMA bulk ring (R10, -34%), batch fusion (R11, -142%),
// L1 bypass (R12), write-through (R14) all failed to move the ~127us LTS
// drain equilibrium for random 8 KB row gathers on sm_103a.
__global__ __launch_bounds__(64, 10)
void geodcd_kernel(const float4* __restrict__ z4,
                   const int*    __restrict__ nbr,
                   const float*  __restrict__ adj,
                   const float*  __restrict__ bw,
                   const float*  __restrict__ cc,
                   float4*       __restrict__ out4)
{
    const int n   = blockIdx.x;
    const int b   = blockIdx.y;
    const int tid = threadIdx.x;   // 64 threads
    const int c4  = tid & 15;
    const int th  = tid >> 4;      // 0..3

    __shared__ float ws[Kv * Cv];     // [k][c] effective edge weights (4 KB)
    __shared__ float scc[NB * Cv];    // transposed channel coeffs [base][c]
    __shared__ float sbw[NB * Kv];    // basis weights for this n [base][k]
    __shared__ float sadj[Kv];

    // ---- cooperative, coalesced staging ----
    {
        const float4 ccv = reinterpret_cast<const float4*>(cc)[tid];
        scc[0 * Cv + tid] = ccv.x;   // transpose to [base][c]
        scc[1 * Cv + tid] = ccv.y;
        scc[2 * Cv + tid] = ccv.z;
        scc[3 * Cv + tid] = ccv.w;
    }
    sbw[tid] = bw[(size_t)th * (Nv * Kv) + n * Kv + c4];  // [base=th][k=c4]
    if (tid < Kv) sadj[tid] = adj[n * Kv + tid];

    // Neighbor index into lane register, packed with its k: (nbr<<4)|k.
    unsigned pk = ((unsigned)nbr[n * Kv + c4] << 4) | (unsigned)c4;

    // 16-element bitonic sort across lanes (lane&15); both half-warps hold
    // identical ascending sequences afterwards.
    #pragma unroll
    for (int size = 2; size <= 16; size <<= 1) {
        #pragma unroll
        for (int stride = size >> 1; stride > 0; stride >>= 1) {
            const unsigned q = __shfl_xor_sync(0xffffffffu, pk, stride);
            const bool dirUp = ((c4 & size) == 0);
            const bool lower = ((c4 & stride) == 0);
            pk = ((lower == dirUp) ? umin(pk, q) : umax(pk, q));
        }
    }
    __syncthreads();

    // ---- weight build: thread computes w[k][4*c4 .. 4*c4+3] for 4 k's ----
    {
        const float4 cb0 = reinterpret_cast<const float4*>(scc + 0 * Cv)[c4];
        const float4 cb1 = reinterpret_cast<const float4*>(scc + 1 * Cv)[c4];
        const float4 cb2 = reinterpret_cast<const float4*>(scc + 2 * Cv)[c4];
        const float4 cb3 = reinterpret_cast<const float4*>(scc + 3 * Cv)[c4];
        #pragma unroll
        for (int p = 0; p < 4; ++p) {
            const int k = th + 4 * p;
            const float a  = sadj[k];
            const float b0 = sbw[0 * Kv + k];
            const float b1 = sbw[1 * Kv + k];
            const float b2 = sbw[2 * Kv + k];
            const float b3 = sbw[3 * Kv + k];
            float4 w;
            w.x = a * (cb0.x * b0 + cb1.x * b1 + cb2.x * b2 + cb3.x * b3);
            w.y = a * (cb0.y * b0 + cb1.y * b1 + cb2.y * b2 + cb3.y * b3);
            w.z = a * (cb0.z * b0 + cb1.z * b1 + cb2.z * b2 + cb3.z * b3);
            w.w = a * (cb0.w * b0 + cb1.w * b1 + cb2.w * b2 + cb3.w * b3);
            reinterpret_cast<float4*>(ws)[k * (Cv / 4) + c4] = w;
        }
    }
    __syncthreads();

    // ---- gather + accumulate, neighbors in ascending index order ----
    const float4* zb = z4 + (size_t)b * Nv * TC4;
    float4* op = out4 + ((size_t)b * Nv + n) * TC4;
    const int sbase = c4 + 16 * th;   // slot for j=0; j-th slot = sbase + 64*j

    float4 acc[8];
    #pragma unroll
    for (int j = 0; j < 8; ++j) acc[j] = make_float4(0.f, 0.f, 0.f, 0.f);

    #pragma unroll
    for (int i = 0; i < Kv; ++i) {
        const unsigned p  = __shfl_sync(0xffffffffu, pk, i);  // sorted elem i
        const int nb = (int)(p >> 4);
        const int k  = (int)(p & 15u);
        const float4 w = reinterpret_cast<const float4*>(ws)[k * (Cv / 4) + c4];
        const float4* row = zb + (size_t)nb * TC4 + sbase;
        #pragma unroll
        for (int j = 0; j < 8; ++j) {
            const float4 zv = __ldg(row + 64 * j);
            acc[j].x = fmaf(zv.x, w.x, acc[j].x);
            acc[j].y = fmaf(zv.y, w.y, acc[j].y);
            acc[j].z = fmaf(zv.z, w.z, acc[j].z);
            acc[j].w = fmaf(zv.w, w.w, acc[j].w);
        }
    }

    #pragma unroll
    for (int j = 0; j < 8; ++j) {
        float4 r;
        r.x = tanhf(acc[j].x);
        r.y = tanhf(acc[j].y);
        r.z = tanhf(acc[j].z);
        r.w = tanhf(acc[j].w);
        __stcs(op + sbase + 64 * j, r);   // streaming store: don't pollute L2
    }
}

extern "C" void kernel_launch(void* const* d_in, const int* in_sizes, int n_in,
                              void* d_out, int out_size) {
    // metadata order: z, neighbor_indices, adjacency, basis_weights, channel_coeffs
    const float4* z4  = (const float4*)d_in[0];
    const int*    nbr = (const int*)   d_in[1];
    const float*  adj = (const float*) d_in[2];
    const float*  bw  = (const float*) d_in[3];
    const float*  cc  = (const float*) d_in[4];
    float4*       o4  = (float4*)      d_out;

    dim3 grid(Nv, Bv);   // b-major wave ordering keeps one batch's z L2-resident
    geodcd_kernel<<<grid, 64>>>(z4, nbr, adj, bw, cc, o4);
}